// round 1
// baseline (speedup 1.0000x reference)
#include <cuda_runtime.h>
#include <math.h>

#define Dd 256
#define Kk 64
#define Nn 64
#define Ll 4096
#define LT 64
#define LP 68
#define AP 68
#define SPLITS 4
#define CHUNK (Ll / SPLITS)
#define NT 256

// Shared memory layout (floats):
//  Ws  : Dd*Kk   = 16384   (W transposed: Ws[d*64+k])
//  Xs  : Dd*LP   = 17408   (X tile, pitch 68 to avoid column bank conflicts)
//  As  : Kk*AP   = 4352    (logits / softmax probs)
//  nrm : 256, rinv: 64, mx: 64, sinv: 64
#define SMEM_FLOATS (Dd * Kk + Dd * LP + Kk * AP + 256 + 64 + 64 + 64)
#define SMEM_BYTES (SMEM_FLOATS * 4)

__device__ float g_S1[Nn][Kk][Dd];   // sum_l a[n,k,l] * xhat[n,d,l]
__device__ float g_S2[Nn][Kk];       // sum_l a[n,k,l]

__global__ void netvlad_zero_kernel() {
    float* p1 = &g_S1[0][0][0];
    size_t n1 = (size_t)Nn * Kk * Dd;
    for (size_t i = (size_t)blockIdx.x * blockDim.x + threadIdx.x; i < n1;
         i += (size_t)gridDim.x * blockDim.x)
        p1[i] = 0.0f;
    float* p2 = &g_S2[0][0];
    size_t n2 = (size_t)Nn * Kk;
    for (size_t i = (size_t)blockIdx.x * blockDim.x + threadIdx.x; i < n2;
         i += (size_t)gridDim.x * blockDim.x)
        p2[i] = 0.0f;
}

__global__ __launch_bounds__(NT, 1)
void netvlad_main(const float* __restrict__ x, const float* __restrict__ w) {
    extern __shared__ float sh[];
    float* Ws   = sh;                  // [Dd][Kk]
    float* Xs   = Ws + Dd * Kk;        // [Dd][LP]
    float* As   = Xs + Dd * LP;        // [Kk][AP]
    float* nrm  = As + Kk * AP;        // [256]
    float* rinv = nrm + 256;           // [64]
    float* mx   = rinv + 64;           // [64]
    float* sinv = mx + 64;             // [64]

    const int tid   = threadIdx.x;
    const int n     = blockIdx.y;
    const int split = blockIdx.x;
    const float* __restrict__ xn = x + (size_t)n * Dd * Ll;

    // Load W transposed into shared: Ws[d*Kk + k] = w[k*Dd + d]
    for (int i = tid; i < Kk * Dd; i += NT) {
        int k = i >> 8;        // i / 256
        int d = i & 255;       // i % 256
        Ws[d * Kk + k] = w[i];
    }

    const int tk = tid >> 4;   // 0..15 -> owns k = 4*tk .. 4*tk+3
    const int tl = tid & 15;   // 0..15 -> owns p = 4*tl..  (GEMM1), d = tl+16*j (GEMM2)

    float acc[4][16];          // S1 slice: [k=4tk+i][d=tl+16*j]
#pragma unroll
    for (int i = 0; i < 4; i++)
#pragma unroll
        for (int j = 0; j < 16; j++) acc[i][j] = 0.0f;
    float s2acc = 0.0f;        // used by tid < 64 (k = tid)

    for (int tile = 0; tile < CHUNK / LT; ++tile) {
        const int l0 = split * CHUNK + tile * LT;
        __syncthreads();  // previous tile's GEMM2 reads done before overwriting Xs/As

        // ---- Load X tile [Dd][LT] (float4, coalesced along l) ----
        for (int idx = tid; idx < Dd * (LT / 4); idx += NT) {
            int d  = idx >> 4;
            int p4 = (idx & 15) << 2;
            float4 v = *reinterpret_cast<const float4*>(xn + (size_t)d * Ll + l0 + p4);
            *reinterpret_cast<float4*>(&Xs[d * LP + p4]) = v;
        }
        __syncthreads();

        // ---- Per-pixel L2 norm over D ----
        {
            int seg = tid >> 6, p = tid & 63;
            float s = 0.0f;
            int dbase = seg * 64;
#pragma unroll 8
            for (int d = 0; d < 64; ++d) {
                float v = Xs[(dbase + d) * LP + p];
                s += v * v;
            }
            nrm[tid] = s;
        }
        __syncthreads();
        if (tid < 64) {
            float t = nrm[tid] + nrm[64 + tid] + nrm[128 + tid] + nrm[192 + tid];
            rinv[tid] = 1.0f / fmaxf(sqrtf(t), 1e-12f);
        }
        __syncthreads();
        // scale tile in place -> xhat
        for (int i = tid; i < Dd * LT; i += NT) {
            int d = i >> 6, p = i & 63;
            Xs[d * LP + p] *= rinv[p];
        }
        __syncthreads();

        // ---- GEMM1: logits[4tk+i][4tl+j] = sum_d W[k,d] * xhat[d,p] ----
        float lg[4][4];
#pragma unroll
        for (int i = 0; i < 4; i++)
#pragma unroll
            for (int j = 0; j < 4; j++) lg[i][j] = 0.0f;
#pragma unroll 4
        for (int d = 0; d < Dd; ++d) {
            float4 wv = *reinterpret_cast<const float4*>(&Ws[d * Kk + 4 * tk]);
            float4 xv = *reinterpret_cast<const float4*>(&Xs[d * LP + 4 * tl]);
            lg[0][0] += wv.x * xv.x; lg[0][1] += wv.x * xv.y; lg[0][2] += wv.x * xv.z; lg[0][3] += wv.x * xv.w;
            lg[1][0] += wv.y * xv.x; lg[1][1] += wv.y * xv.y; lg[1][2] += wv.y * xv.z; lg[1][3] += wv.y * xv.w;
            lg[2][0] += wv.z * xv.x; lg[2][1] += wv.z * xv.y; lg[2][2] += wv.z * xv.z; lg[2][3] += wv.z * xv.w;
            lg[3][0] += wv.w * xv.x; lg[3][1] += wv.w * xv.y; lg[3][2] += wv.w * xv.z; lg[3][3] += wv.w * xv.w;
        }
#pragma unroll
        for (int i = 0; i < 4; i++)
            *reinterpret_cast<float4*>(&As[(4 * tk + i) * AP + 4 * tl]) =
                make_float4(lg[i][0], lg[i][1], lg[i][2], lg[i][3]);
        __syncthreads();

        // ---- Softmax over k for each pixel p ----
        {
            int tq = tid >> 6, p = tid & 63;
            float m = -1e30f;
            int kb = tq * 16;
#pragma unroll 4
            for (int k = 0; k < 16; ++k) m = fmaxf(m, As[(kb + k) * AP + p]);
            nrm[tid] = m;
        }
        __syncthreads();
        if (tid < 64) {
            float m = fmaxf(fmaxf(nrm[tid], nrm[64 + tid]),
                            fmaxf(nrm[128 + tid], nrm[192 + tid]));
            mx[tid] = m;
        }
        __syncthreads();
        {
            int tq = tid >> 6, p = tid & 63;
            float m = mx[p];
            float s = 0.0f;
            int kb = tq * 16;
#pragma unroll 4
            for (int k = 0; k < 16; ++k) {
                float e = __expf(As[(kb + k) * AP + p] - m);
                As[(kb + k) * AP + p] = e;
                s += e;
            }
            nrm[tid] = s;
        }
        __syncthreads();
        if (tid < 64) {
            float s = nrm[tid] + nrm[64 + tid] + nrm[128 + tid] + nrm[192 + tid];
            sinv[tid] = 1.0f / s;
        }
        __syncthreads();
        for (int i = tid; i < Kk * LT; i += NT) {
            int k = i >> 6, p = i & 63;
            As[k * AP + p] *= sinv[p];
        }
        __syncthreads();

        // S2 partial sums (k = tid)
        if (tid < 64) {
            float s = 0.0f;
#pragma unroll 8
            for (int p = 0; p < 64; ++p) s += As[tid * AP + p];
            s2acc += s;
        }

        // ---- GEMM2: acc[k][d] += sum_p a[k,p] * xhat[d,p] ----
#pragma unroll 1
        for (int pc = 0; pc < LT; pc += 4) {
            float4 av[4];
#pragma unroll
            for (int i = 0; i < 4; i++)
                av[i] = *reinterpret_cast<const float4*>(&As[(4 * tk + i) * AP + pc]);
#pragma unroll
            for (int jh = 0; jh < 2; ++jh) {
                float4 xr[8];
#pragma unroll
                for (int j = 0; j < 8; j++)
                    xr[j] = *reinterpret_cast<const float4*>(
                        &Xs[(tl + 16 * (jh * 8 + j)) * LP + pc]);
#pragma unroll
                for (int i = 0; i < 4; i++) {
#pragma unroll
                    for (int j = 0; j < 8; j++) {
                        float a0 = acc[i][jh * 8 + j];
                        a0 += av[i].x * xr[j].x;
                        a0 += av[i].y * xr[j].y;
                        a0 += av[i].z * xr[j].z;
                        a0 += av[i].w * xr[j].w;
                        acc[i][jh * 8 + j] = a0;
                    }
                }
            }
        }
    }

    // ---- Flush partials ----
#pragma unroll
    for (int i = 0; i < 4; i++)
#pragma unroll
        for (int j = 0; j < 16; j++)
            atomicAdd(&g_S1[n][4 * tk + i][tl + 16 * j], acc[i][j]);
    if (tid < 64) atomicAdd(&g_S2[n][tid], s2acc);
}

__global__ __launch_bounds__(256)
void netvlad_finalize(const float* __restrict__ cent, float* __restrict__ out) {
    const int n = blockIdx.x;
    const int d = threadIdx.x;      // 0..255, one d per thread
    const int lane = d & 31, wid = d >> 5;
    __shared__ float red[8];
    __shared__ float tot;

    float val[Kk];
    float gsum = 0.0f;

    for (int k = 0; k < Kk; ++k) {
        float v = g_S1[n][k][d] - g_S2[n][k] * cent[k * Dd + d];
        float s = v * v;
#pragma unroll
        for (int o = 16; o > 0; o >>= 1) s += __shfl_down_sync(0xffffffffu, s, o);
        if (lane == 0) red[wid] = s;
        __syncthreads();
        if (d == 0) {
            float t = 0.0f;
#pragma unroll
            for (int w2 = 0; w2 < 8; w2++) t += red[w2];
            tot = t;
        }
        __syncthreads();
        float inv = 1.0f / fmaxf(sqrtf(tot), 1e-12f);
        v *= inv;
        val[k] = v;
        gsum += v * v;
    }

#pragma unroll
    for (int o = 16; o > 0; o >>= 1) gsum += __shfl_down_sync(0xffffffffu, gsum, o);
    if (lane == 0) red[wid] = gsum;
    __syncthreads();
    if (d == 0) {
        float t = 0.0f;
#pragma unroll
        for (int w2 = 0; w2 < 8; w2++) t += red[w2];
        tot = 1.0f / fmaxf(sqrtf(t), 1e-12f);
    }
    __syncthreads();
    float ginv = tot;

    size_t base = (size_t)n * Kk * Dd;
#pragma unroll 4
    for (int k = 0; k < Kk; ++k)
        out[base + k * Dd + d] = val[k] * ginv;
}

extern "C" void kernel_launch(void* const* d_in, const int* in_sizes, int n_in,
                              void* d_out, int out_size) {
    const float* x = (const float*)d_in[0];
    const float* w = (const float*)d_in[1];
    const float* c = (const float*)d_in[2];
    float* out = (float*)d_out;

    cudaFuncSetAttribute(netvlad_main,
                         cudaFuncAttributeMaxDynamicSharedMemorySize, SMEM_BYTES);

    netvlad_zero_kernel<<<2048, 256>>>();

    dim3 grid(SPLITS, Nn);
    netvlad_main<<<grid, NT, SMEM_BYTES>>>(x, w);

    netvlad_finalize<<<Nn, 256>>>(c, out);
}

// round 2
// speedup vs baseline: 1.0029x; 1.0029x over previous
#include <cuda_runtime.h>
#include <math.h>

#define Dd 256
#define Kk 64
#define Nn 64
#define Ll 4096
#define LT 64
#define LP 68
#define AP 68
#define SPLITS 4
#define CHUNK (Ll / SPLITS)
#define NT 256

// Shared memory layout (floats):
//  Ws  : Dd*Kk   = 16384   (W transposed: Ws[d*64+k])
//  Xs  : Dd*LP   = 17408   (X tile, pitch 68 to avoid column bank conflicts)
//  As  : Kk*AP   = 4352    (logits / softmax probs)
//  nrm : 256, rinv: 64, mx: 64, sinv: 64
#define SMEM_FLOATS (Dd * Kk + Dd * LP + Kk * AP + 256 + 64 + 64 + 64)
#define SMEM_BYTES (SMEM_FLOATS * 4)

__device__ float g_S1[Nn][Kk][Dd];   // sum_l a[n,k,l] * xhat[n,d,l]
__device__ float g_S2[Nn][Kk];       // sum_l a[n,k,l]

__global__ void netvlad_zero_kernel() {
    float* p1 = &g_S1[0][0][0];
    size_t n1 = (size_t)Nn * Kk * Dd;
    for (size_t i = (size_t)blockIdx.x * blockDim.x + threadIdx.x; i < n1;
         i += (size_t)gridDim.x * blockDim.x)
        p1[i] = 0.0f;
    float* p2 = &g_S2[0][0];
    size_t n2 = (size_t)Nn * Kk;
    for (size_t i = (size_t)blockIdx.x * blockDim.x + threadIdx.x; i < n2;
         i += (size_t)gridDim.x * blockDim.x)
        p2[i] = 0.0f;
}

__global__ __launch_bounds__(NT, 1)
void netvlad_main(const float* __restrict__ x, const float* __restrict__ w) {
    extern __shared__ float sh[];
    float* Ws   = sh;                  // [Dd][Kk]
    float* Xs   = Ws + Dd * Kk;        // [Dd][LP]
    float* As   = Xs + Dd * LP;        // [Kk][AP]
    float* nrm  = As + Kk * AP;        // [256]
    float* rinv = nrm + 256;           // [64]
    float* mx   = rinv + 64;           // [64]
    float* sinv = mx + 64;             // [64]

    const int tid   = threadIdx.x;
    const int n     = blockIdx.y;
    const int split = blockIdx.x;
    const float* __restrict__ xn = x + (size_t)n * Dd * Ll;

    // Load W transposed into shared: Ws[d*Kk + k] = w[k*Dd + d]
    for (int i = tid; i < Kk * Dd; i += NT) {
        int k = i >> 8;        // i / 256
        int d = i & 255;       // i % 256
        Ws[d * Kk + k] = w[i];
    }

    const int tk = tid >> 4;   // 0..15 -> owns k = 4*tk .. 4*tk+3
    const int tl = tid & 15;   // 0..15 -> owns p = 4*tl..  (GEMM1), d = tl+16*j (GEMM2)

    float acc[4][16];          // S1 slice: [k=4tk+i][d=tl+16*j]
#pragma unroll
    for (int i = 0; i < 4; i++)
#pragma unroll
        for (int j = 0; j < 16; j++) acc[i][j] = 0.0f;
    float s2acc = 0.0f;        // used by tid < 64 (k = tid)

    for (int tile = 0; tile < CHUNK / LT; ++tile) {
        const int l0 = split * CHUNK + tile * LT;
        __syncthreads();  // previous tile's GEMM2 reads done before overwriting Xs/As

        // ---- Load X tile [Dd][LT] (float4, coalesced along l) ----
        for (int idx = tid; idx < Dd * (LT / 4); idx += NT) {
            int d  = idx >> 4;
            int p4 = (idx & 15) << 2;
            float4 v = *reinterpret_cast<const float4*>(xn + (size_t)d * Ll + l0 + p4);
            *reinterpret_cast<float4*>(&Xs[d * LP + p4]) = v;
        }
        __syncthreads();

        // ---- Per-pixel L2 norm over D ----
        {
            int seg = tid >> 6, p = tid & 63;
            float s = 0.0f;
            int dbase = seg * 64;
#pragma unroll 8
            for (int d = 0; d < 64; ++d) {
                float v = Xs[(dbase + d) * LP + p];
                s += v * v;
            }
            nrm[tid] = s;
        }
        __syncthreads();
        if (tid < 64) {
            float t = nrm[tid] + nrm[64 + tid] + nrm[128 + tid] + nrm[192 + tid];
            rinv[tid] = 1.0f / fmaxf(sqrtf(t), 1e-12f);
        }
        __syncthreads();
        // scale tile in place -> xhat
        for (int i = tid; i < Dd * LT; i += NT) {
            int d = i >> 6, p = i & 63;
            Xs[d * LP + p] *= rinv[p];
        }
        __syncthreads();

        // ---- GEMM1: logits[4tk+i][4tl+j] = sum_d W[k,d] * xhat[d,p] ----
        float lg[4][4];
#pragma unroll
        for (int i = 0; i < 4; i++)
#pragma unroll
            for (int j = 0; j < 4; j++) lg[i][j] = 0.0f;
#pragma unroll 4
        for (int d = 0; d < Dd; ++d) {
            float4 wv = *reinterpret_cast<const float4*>(&Ws[d * Kk + 4 * tk]);
            float4 xv = *reinterpret_cast<const float4*>(&Xs[d * LP + 4 * tl]);
            lg[0][0] += wv.x * xv.x; lg[0][1] += wv.x * xv.y; lg[0][2] += wv.x * xv.z; lg[0][3] += wv.x * xv.w;
            lg[1][0] += wv.y * xv.x; lg[1][1] += wv.y * xv.y; lg[1][2] += wv.y * xv.z; lg[1][3] += wv.y * xv.w;
            lg[2][0] += wv.z * xv.x; lg[2][1] += wv.z * xv.y; lg[2][2] += wv.z * xv.z; lg[2][3] += wv.z * xv.w;
            lg[3][0] += wv.w * xv.x; lg[3][1] += wv.w * xv.y; lg[3][2] += wv.w * xv.z; lg[3][3] += wv.w * xv.w;
        }
#pragma unroll
        for (int i = 0; i < 4; i++)
            *reinterpret_cast<float4*>(&As[(4 * tk + i) * AP + 4 * tl]) =
                make_float4(lg[i][0], lg[i][1], lg[i][2], lg[i][3]);
        __syncthreads();

        // ---- Softmax over k for each pixel p ----
        {
            int tq = tid >> 6, p = tid & 63;
            float m = -1e30f;
            int kb = tq * 16;
#pragma unroll 4
            for (int k = 0; k < 16; ++k) m = fmaxf(m, As[(kb + k) * AP + p]);
            nrm[tid] = m;
        }
        __syncthreads();
        if (tid < 64) {
            float m = fmaxf(fmaxf(nrm[tid], nrm[64 + tid]),
                            fmaxf(nrm[128 + tid], nrm[192 + tid]));
            mx[tid] = m;
        }
        __syncthreads();
        {
            int tq = tid >> 6, p = tid & 63;
            float m = mx[p];
            float s = 0.0f;
            int kb = tq * 16;
#pragma unroll 4
            for (int k = 0; k < 16; ++k) {
                float e = __expf(As[(kb + k) * AP + p] - m);
                As[(kb + k) * AP + p] = e;
                s += e;
            }
            nrm[tid] = s;
        }
        __syncthreads();
        if (tid < 64) {
            float s = nrm[tid] + nrm[64 + tid] + nrm[128 + tid] + nrm[192 + tid];
            sinv[tid] = 1.0f / s;
        }
        __syncthreads();
        for (int i = tid; i < Kk * LT; i += NT) {
            int k = i >> 6, p = i & 63;
            As[k * AP + p] *= sinv[p];
        }
        __syncthreads();

        // S2 partial sums (k = tid)
        if (tid < 64) {
            float s = 0.0f;
#pragma unroll 8
            for (int p = 0; p < 64; ++p) s += As[tid * AP + p];
            s2acc += s;
        }

        // ---- GEMM2: acc[k][d] += sum_p a[k,p] * xhat[d,p] ----
#pragma unroll 1
        for (int pc = 0; pc < LT; pc += 4) {
            float4 av[4];
#pragma unroll
            for (int i = 0; i < 4; i++)
                av[i] = *reinterpret_cast<const float4*>(&As[(4 * tk + i) * AP + pc]);
#pragma unroll
            for (int jh = 0; jh < 2; ++jh) {
                float4 xr[8];
#pragma unroll
                for (int j = 0; j < 8; j++)
                    xr[j] = *reinterpret_cast<const float4*>(
                        &Xs[(tl + 16 * (jh * 8 + j)) * LP + pc]);
#pragma unroll
                for (int i = 0; i < 4; i++) {
#pragma unroll
                    for (int j = 0; j < 8; j++) {
                        float a0 = acc[i][jh * 8 + j];
                        a0 += av[i].x * xr[j].x;
                        a0 += av[i].y * xr[j].y;
                        a0 += av[i].z * xr[j].z;
                        a0 += av[i].w * xr[j].w;
                        acc[i][jh * 8 + j] = a0;
                    }
                }
            }
        }
    }

    // ---- Flush partials ----
#pragma unroll
    for (int i = 0; i < 4; i++)
#pragma unroll
        for (int j = 0; j < 16; j++)
            atomicAdd(&g_S1[n][4 * tk + i][tl + 16 * j], acc[i][j]);
    if (tid < 64) atomicAdd(&g_S2[n][tid], s2acc);
}

__global__ __launch_bounds__(256)
void netvlad_finalize(const float* __restrict__ cent, float* __restrict__ out) {
    const int n = blockIdx.x;
    const int d = threadIdx.x;      // 0..255, one d per thread
    const int lane = d & 31, wid = d >> 5;
    __shared__ float red[8];
    __shared__ float tot;

    float val[Kk];
    float gsum = 0.0f;

    for (int k = 0; k < Kk; ++k) {
        float v = g_S1[n][k][d] - g_S2[n][k] * cent[k * Dd + d];
        float s = v * v;
#pragma unroll
        for (int o = 16; o > 0; o >>= 1) s += __shfl_down_sync(0xffffffffu, s, o);
        if (lane == 0) red[wid] = s;
        __syncthreads();
        if (d == 0) {
            float t = 0.0f;
#pragma unroll
            for (int w2 = 0; w2 < 8; w2++) t += red[w2];
            tot = t;
        }
        __syncthreads();
        float inv = 1.0f / fmaxf(sqrtf(tot), 1e-12f);
        v *= inv;
        val[k] = v;
        gsum += v * v;
    }

#pragma unroll
    for (int o = 16; o > 0; o >>= 1) gsum += __shfl_down_sync(0xffffffffu, gsum, o);
    if (lane == 0) red[wid] = gsum;
    __syncthreads();
    if (d == 0) {
        float t = 0.0f;
#pragma unroll
        for (int w2 = 0; w2 < 8; w2++) t += red[w2];
        tot = 1.0f / fmaxf(sqrtf(t), 1e-12f);
    }
    __syncthreads();
    float ginv = tot;

    size_t base = (size_t)n * Kk * Dd;
#pragma unroll 4
    for (int k = 0; k < Kk; ++k)
        out[base + k * Dd + d] = val[k] * ginv;
}

extern "C" void kernel_launch(void* const* d_in, const int* in_sizes, int n_in,
                              void* d_out, int out_size) {
    const float* x = (const float*)d_in[0];
    const float* w = (const float*)d_in[1];
    const float* c = (const float*)d_in[2];
    float* out = (float*)d_out;

    cudaFuncSetAttribute(netvlad_main,
                         cudaFuncAttributeMaxDynamicSharedMemorySize, SMEM_BYTES);

    netvlad_zero_kernel<<<2048, 256>>>();

    dim3 grid(SPLITS, Nn);
    netvlad_main<<<grid, NT, SMEM_BYTES>>>(x, w);

    netvlad_finalize<<<Nn, 256>>>(c, out);
}